// round 2
// baseline (speedup 1.0000x reference)
#include <cuda_runtime.h>

#define FULLMASK 0xffffffffu

#define BB 4096
#define TT 128
#define DD 32
#define HH 64
#define G3 192  // 3*H

// smem float offsets
#define O_WIH0T 0                   // [32][192]
#define O_WHH0T (32 * G3)           // [64][192]
#define O_WIH1T (O_WHH0T + 64 * G3) // [64][192]
#define O_WHH1T (O_WIH1T + 64 * G3) // [64][192]
#define O_BI0   (O_WHH1T + 64 * G3)
#define O_BH0   (O_BI0 + G3)
#define O_BI1   (O_BH0 + G3)
#define O_BH1   (O_BI1 + G3)
#define SMEM_FLOATS (O_BH1 + G3)
#define SMEM_BYTES (SMEM_FLOATS * 4)

__device__ __forceinline__ float sigmoid_f(float v) {
    return 1.0f / (1.0f + __expf(-v));
}
__device__ __forceinline__ float tanh_f(float v) {
    float e = __expf(-2.0f * v);
    return (1.0f - e) / (1.0f + e);
}

// Accumulate gemv over a 64-long input vector distributed across the warp:
// input[2m] lives in (ha) of lane m, input[2m+1] in (hb) of lane m.
// w2: transposed weights as float2 rows of 96 ([k][192] floats).
// Accumulates r, z, n gates for 2 units (A=2*lane, B=2*lane+1) x 2 batches.
__device__ __forceinline__ void mv64(
    const float2* __restrict__ w2, int lane,
    float ha0, float hb0, float ha1, float hb1,
    float& rA0, float& rB0, float& rA1, float& rB1,
    float& zA0, float& zB0, float& zA1, float& zB1,
    float& nA0, float& nB0, float& nA1, float& nB1)
{
#pragma unroll 8
    for (int m = 0; m < 32; ++m) {
        float va0 = __shfl_sync(FULLMASK, ha0, m);
        float vb0 = __shfl_sync(FULLMASK, hb0, m);
        float va1 = __shfl_sync(FULLMASK, ha1, m);
        float vb1 = __shfl_sync(FULLMASK, hb1, m);
        const float2* rowe = w2 + (2 * m) * 96;
        const float2* rowo = rowe + 96;
        float2 wre = rowe[lane], wze = rowe[32 + lane], wne = rowe[64 + lane];
        float2 wro = rowo[lane], wzo = rowo[32 + lane], wno = rowo[64 + lane];
        rA0 = fmaf(wre.x, va0, rA0); rA0 = fmaf(wro.x, vb0, rA0);
        rB0 = fmaf(wre.y, va0, rB0); rB0 = fmaf(wro.y, vb0, rB0);
        rA1 = fmaf(wre.x, va1, rA1); rA1 = fmaf(wro.x, vb1, rA1);
        rB1 = fmaf(wre.y, va1, rB1); rB1 = fmaf(wro.y, vb1, rB1);
        zA0 = fmaf(wze.x, va0, zA0); zA0 = fmaf(wzo.x, vb0, zA0);
        zB0 = fmaf(wze.y, va0, zB0); zB0 = fmaf(wzo.y, vb0, zB0);
        zA1 = fmaf(wze.x, va1, zA1); zA1 = fmaf(wzo.x, vb1, zA1);
        zB1 = fmaf(wze.y, va1, zB1); zB1 = fmaf(wzo.y, vb1, zB1);
        nA0 = fmaf(wne.x, va0, nA0); nA0 = fmaf(wno.x, vb0, nA0);
        nB0 = fmaf(wne.y, va0, nB0); nB0 = fmaf(wno.y, vb0, nB0);
        nA1 = fmaf(wne.x, va1, nA1); nA1 = fmaf(wno.x, vb1, nA1);
        nB1 = fmaf(wne.y, va1, nB1); nB1 = fmaf(wno.y, vb1, nB1);
    }
}

// Same but over a 32-long vector held one-element-per-lane (x_t).
__device__ __forceinline__ void mv32(
    const float2* __restrict__ w2, int lane,
    float xt0, float xt1,
    float& rA0, float& rB0, float& rA1, float& rB1,
    float& zA0, float& zB0, float& zA1, float& zB1,
    float& nA0, float& nB0, float& nA1, float& nB1)
{
#pragma unroll 8
    for (int k = 0; k < 32; ++k) {
        float a0 = __shfl_sync(FULLMASK, xt0, k);
        float a1 = __shfl_sync(FULLMASK, xt1, k);
        const float2* row = w2 + k * 96;
        float2 wr = row[lane], wz = row[32 + lane], wn = row[64 + lane];
        rA0 = fmaf(wr.x, a0, rA0); rB0 = fmaf(wr.y, a0, rB0);
        rA1 = fmaf(wr.x, a1, rA1); rB1 = fmaf(wr.y, a1, rB1);
        zA0 = fmaf(wz.x, a0, zA0); zB0 = fmaf(wz.y, a0, zB0);
        zA1 = fmaf(wz.x, a1, zA1); zB1 = fmaf(wz.y, a1, zB1);
        nA0 = fmaf(wn.x, a0, nA0); nB0 = fmaf(wn.y, a0, nB0);
        nA1 = fmaf(wn.x, a1, nA1); nB1 = fmaf(wn.y, a1, nB1);
    }
}

extern __shared__ float smem[];

__global__ void __launch_bounds__(512, 1)
gru_fused_kernel(const float* __restrict__ x,
                 const float* __restrict__ Wih0, const float* __restrict__ Whh0,
                 const float* __restrict__ bih0, const float* __restrict__ bhh0,
                 const float* __restrict__ Wih1, const float* __restrict__ Whh1,
                 const float* __restrict__ bih1, const float* __restrict__ bhh1,
                 const float* __restrict__ fcw, const float* __restrict__ fcb,
                 float* __restrict__ out)
{
    const int tid = threadIdx.x;

    // ---- cooperative load: transpose weights into smem ----
    for (int i = tid; i < G3 * DD; i += blockDim.x) {
        int j = i / DD, k = i % DD;
        smem[O_WIH0T + k * G3 + j] = Wih0[i];
    }
    for (int i = tid; i < G3 * HH; i += blockDim.x) {
        int j = i / HH, k = i % HH;
        smem[O_WHH0T + k * G3 + j] = Whh0[i];
        smem[O_WIH1T + k * G3 + j] = Wih1[i];
        smem[O_WHH1T + k * G3 + j] = Whh1[i];
    }
    if (tid < G3) {
        smem[O_BI0 + tid] = bih0[tid];
        smem[O_BH0 + tid] = bhh0[tid];
        smem[O_BI1 + tid] = bih1[tid];
        smem[O_BH1 + tid] = bhh1[tid];
    }
    __syncthreads();

    const int warp = tid >> 5;
    const int lane = tid & 31;
    const int gw = blockIdx.x * 16 + warp;  // global warp id
    const int b0 = gw * 2;
    const int b1 = b0 + 1;

    const int u0 = 2 * lane;
    const int u1 = u0 + 1;

    // bias constants (combined for r,z; separate for n's x/h parts)
    const float rb0A = smem[O_BI0 + u0] + smem[O_BH0 + u0];
    const float rb0B = smem[O_BI0 + u1] + smem[O_BH0 + u1];
    const float zb0A = smem[O_BI0 + 64 + u0] + smem[O_BH0 + 64 + u0];
    const float zb0B = smem[O_BI0 + 64 + u1] + smem[O_BH0 + 64 + u1];
    const float nxb0A = smem[O_BI0 + 128 + u0];
    const float nxb0B = smem[O_BI0 + 128 + u1];
    const float nhb0A = smem[O_BH0 + 128 + u0];
    const float nhb0B = smem[O_BH0 + 128 + u1];

    const float rb1A = smem[O_BI1 + u0] + smem[O_BH1 + u0];
    const float rb1B = smem[O_BI1 + u1] + smem[O_BH1 + u1];
    const float zb1A = smem[O_BI1 + 64 + u0] + smem[O_BH1 + 64 + u0];
    const float zb1B = smem[O_BI1 + 64 + u1] + smem[O_BH1 + 64 + u1];
    const float nxb1A = smem[O_BI1 + 128 + u0];
    const float nxb1B = smem[O_BI1 + 128 + u1];
    const float nhb1A = smem[O_BH1 + 128 + u0];
    const float nhb1B = smem[O_BH1 + 128 + u1];

    const float2* wih0 = (const float2*)(smem + O_WIH0T);
    const float2* whh0 = (const float2*)(smem + O_WHH0T);
    const float2* wih1 = (const float2*)(smem + O_WIH1T);
    const float2* whh1 = (const float2*)(smem + O_WHH1T);

    // states
    float h1a0 = 0.f, h1b0 = 0.f, h1a1 = 0.f, h1b1 = 0.f;
    float h2a0 = 0.f, h2b0 = 0.f, h2a1 = 0.f, h2b1 = 0.f;

    const float* xp0 = x + (size_t)b0 * (TT * DD) + lane;
    const float* xp1 = x + (size_t)b1 * (TT * DD) + lane;

    for (int t = 0; t < TT; ++t) {
        float xt0 = xp0[t * DD];
        float xt1 = xp1[t * DD];

        // ---------------- layer 1 ----------------
        float rA0 = rb0A, rB0 = rb0B, rA1 = rb0A, rB1 = rb0B;
        float zA0 = zb0A, zB0 = zb0B, zA1 = zb0A, zB1 = zb0B;
        float nxA0 = nxb0A, nxB0 = nxb0B, nxA1 = nxb0A, nxB1 = nxb0B;
        float nhA0 = nhb0A, nhB0 = nhb0B, nhA1 = nhb0A, nhB1 = nhb0B;

        mv32(wih0, lane, xt0, xt1,
             rA0, rB0, rA1, rB1, zA0, zB0, zA1, zB1, nxA0, nxB0, nxA1, nxB1);
        mv64(whh0, lane, h1a0, h1b0, h1a1, h1b1,
             rA0, rB0, rA1, rB1, zA0, zB0, zA1, zB1, nhA0, nhB0, nhA1, nhB1);

        {
            float r, z, n;
            r = sigmoid_f(rA0); z = sigmoid_f(zA0);
            n = tanh_f(nxA0 + r * nhA0); h1a0 = n + z * (h1a0 - n);
            r = sigmoid_f(rB0); z = sigmoid_f(zB0);
            n = tanh_f(nxB0 + r * nhB0); h1b0 = n + z * (h1b0 - n);
            r = sigmoid_f(rA1); z = sigmoid_f(zA1);
            n = tanh_f(nxA1 + r * nhA1); h1a1 = n + z * (h1a1 - n);
            r = sigmoid_f(rB1); z = sigmoid_f(zB1);
            n = tanh_f(nxB1 + r * nhB1); h1b1 = n + z * (h1b1 - n);
        }

        // ---------------- layer 2 ----------------
        rA0 = rb1A; rB0 = rb1B; rA1 = rb1A; rB1 = rb1B;
        zA0 = zb1A; zB0 = zb1B; zA1 = zb1A; zB1 = zb1B;
        nxA0 = nxb1A; nxB0 = nxb1B; nxA1 = nxb1A; nxB1 = nxb1B;
        nhA0 = nhb1A; nhB0 = nhb1B; nhA1 = nhb1A; nhB1 = nhb1B;

        // input part (h1_new through W_ih1): r,z,nx
        mv64(wih1, lane, h1a0, h1b0, h1a1, h1b1,
             rA0, rB0, rA1, rB1, zA0, zB0, zA1, zB1, nxA0, nxB0, nxA1, nxB1);
        // hidden part (h2 through W_hh1): r,z,nh
        mv64(whh1, lane, h2a0, h2b0, h2a1, h2b1,
             rA0, rB0, rA1, rB1, zA0, zB0, zA1, zB1, nhA0, nhB0, nhA1, nhB1);

        {
            float r, z, n;
            r = sigmoid_f(rA0); z = sigmoid_f(zA0);
            n = tanh_f(nxA0 + r * nhA0); h2a0 = n + z * (h2a0 - n);
            r = sigmoid_f(rB0); z = sigmoid_f(zB0);
            n = tanh_f(nxB0 + r * nhB0); h2b0 = n + z * (h2b0 - n);
            r = sigmoid_f(rA1); z = sigmoid_f(zA1);
            n = tanh_f(nxA1 + r * nhA1); h2a1 = n + z * (h2a1 - n);
            r = sigmoid_f(rB1); z = sigmoid_f(zB1);
            n = tanh_f(nxB1 + r * nhB1); h2b1 = n + z * (h2b1 - n);
        }
    }

    // ---- final FC: out[b] = h2 . fc_w + fc_b ----
    float w0 = fcw[u0], w1 = fcw[u1];
    float p0 = h2a0 * w0 + h2b0 * w1;
    float p1 = h2a1 * w0 + h2b1 * w1;
#pragma unroll
    for (int off = 16; off > 0; off >>= 1) {
        p0 += __shfl_xor_sync(FULLMASK, p0, off);
        p1 += __shfl_xor_sync(FULLMASK, p1, off);
    }
    if (lane == 0) {
        float bias = fcb[0];
        out[b0] = p0 + bias;
        out[b1] = p1 + bias;
    }
}

extern "C" void kernel_launch(void* const* d_in, const int* in_sizes, int n_in,
                              void* d_out, int out_size)
{
    const float* x    = (const float*)d_in[0];
    const float* Wih0 = (const float*)d_in[1];
    const float* Whh0 = (const float*)d_in[2];
    const float* bih0 = (const float*)d_in[3];
    const float* bhh0 = (const float*)d_in[4];
    const float* Wih1 = (const float*)d_in[5];
    const float* Whh1 = (const float*)d_in[6];
    const float* bih1 = (const float*)d_in[7];
    const float* bhh1 = (const float*)d_in[8];
    const float* fcw  = (const float*)d_in[9];
    const float* fcb  = (const float*)d_in[10];
    float* out = (float*)d_out;

    cudaFuncSetAttribute(gru_fused_kernel,
                         cudaFuncAttributeMaxDynamicSharedMemorySize, SMEM_BYTES);

    // 4096 batches / (2 per warp * 16 warps per block) = 128 blocks
    gru_fused_kernel<<<128, 512, SMEM_BYTES>>>(
        x, Wih0, Whh0, bih0, bhh0, Wih1, Whh1, bih1, bhh1, fcw, fcb, out);
}

// round 7
// speedup vs baseline: 1.2668x; 1.2668x over previous
#include <cuda_runtime.h>

#define FULLMASK 0xffffffffu

#define TT 128
#define DD 32
#define HH 64
#define G3 192

#define WARPS 8
#define RB 4                 // batches per warp
#define THREADS (WARPS * 32)
#define BATCH_PER_BLOCK (WARPS * RB)   // 32
#define NBLOCKS 128                    // 4096 / 32

// ---- smem layout (floats) ----
#define O_WIH0T 0                        // [32][192] transposed
#define O_WHH0T (O_WIH0T + DD * G3)      // [64][192]
#define O_WIH1T (O_WHH0T + HH * G3)      // [64][192]
#define O_WHH1T (O_WIH1T + HH * G3)      // [64][192]
#define O_BI0   (O_WHH1T + HH * G3)
#define O_BH0   (O_BI0 + G3)
#define O_BI1   (O_BH0 + G3)
#define O_BH1   (O_BI1 + G3)
#define O_HBUF  (O_BH1 + G3)             // per warp: h1[RB][64], h2[RB][64]
#define HBUF_PER_WARP (2 * RB * HH)
#define SMEM_FLOATS (O_HBUF + WARPS * HBUF_PER_WARP)
#define SMEM_BYTES (SMEM_FLOATS * 4)

__device__ __forceinline__ float sigmoid_f(float v) {
    return 1.0f / (1.0f + __expf(-v));
}
__device__ __forceinline__ float tanh_f(float v) {
    float e = __expf(-2.0f * v);
    return (1.0f - e) / (1.0f + e);
}

// gemv over 64-long h vector held in warp-private smem buffer hb[RB][64].
// w2: float2 view of transposed weights ([k][192] floats -> rows of 96 float2).
// lane owns units (2*lane, 2*lane+1); accumulates 3 gates x 2 units x RB batches.
__device__ __forceinline__ void mv64_s(
    const float2* __restrict__ w2, const float* __restrict__ hb, int lane,
    float rA[RB], float rB[RB], float zA[RB], float zB[RB],
    float nA[RB], float nB[RB])
{
#pragma unroll 8
    for (int m = 0; m < 32; ++m) {
        const float2* rowe = w2 + (2 * m) * 96;
        const float2* rowo = rowe + 96;
        float2 wre = rowe[lane], wze = rowe[32 + lane], wne = rowe[64 + lane];
        float2 wro = rowo[lane], wzo = rowo[32 + lane], wno = rowo[64 + lane];
#pragma unroll
        for (int b = 0; b < RB; ++b) {
            // broadcast LDS.64: all lanes read the same address (N=1, 1 wavefront)
            float2 hv = *(const float2*)(hb + b * HH + 2 * m);
            rA[b] = fmaf(wre.x, hv.x, rA[b]); rA[b] = fmaf(wro.x, hv.y, rA[b]);
            rB[b] = fmaf(wre.y, hv.x, rB[b]); rB[b] = fmaf(wro.y, hv.y, rB[b]);
            zA[b] = fmaf(wze.x, hv.x, zA[b]); zA[b] = fmaf(wzo.x, hv.y, zA[b]);
            zB[b] = fmaf(wze.y, hv.x, zB[b]); zB[b] = fmaf(wzo.y, hv.y, zB[b]);
            nA[b] = fmaf(wne.x, hv.x, nA[b]); nA[b] = fmaf(wno.x, hv.y, nA[b]);
            nB[b] = fmaf(wne.y, hv.x, nB[b]); nB[b] = fmaf(wno.y, hv.y, nB[b]);
        }
    }
}

// gemv over 32-long x vector held per-lane in registers (lane k owns x[k]).
__device__ __forceinline__ void mv32_s(
    const float2* __restrict__ w2, int lane, const float xt[RB],
    float rA[RB], float rB[RB], float zA[RB], float zB[RB],
    float nA[RB], float nB[RB])
{
#pragma unroll 8
    for (int k = 0; k < 32; ++k) {
        const float2* row = w2 + k * 96;
        float2 wr = row[lane], wz = row[32 + lane], wn = row[64 + lane];
#pragma unroll
        for (int b = 0; b < RB; ++b) {
            float a = __shfl_sync(FULLMASK, xt[b], k);
            rA[b] = fmaf(wr.x, a, rA[b]); rB[b] = fmaf(wr.y, a, rB[b]);
            zA[b] = fmaf(wz.x, a, zA[b]); zB[b] = fmaf(wz.y, a, zB[b]);
            nA[b] = fmaf(wn.x, a, nA[b]); nB[b] = fmaf(wn.y, a, nB[b]);
        }
    }
}

extern __shared__ float smem[];

__global__ void __launch_bounds__(THREADS, 1)
gru_fused_kernel(const float* __restrict__ x,
                 const float* __restrict__ Wih0, const float* __restrict__ Whh0,
                 const float* __restrict__ bih0, const float* __restrict__ bhh0,
                 const float* __restrict__ Wih1, const float* __restrict__ Whh1,
                 const float* __restrict__ bih1, const float* __restrict__ bhh1,
                 const float* __restrict__ fcw, const float* __restrict__ fcb,
                 float* __restrict__ out)
{
    const int tid = threadIdx.x;

    // ---- cooperative load: transpose weights into smem ----
    for (int i = tid; i < G3 * DD; i += THREADS) {
        int j = i / DD, k = i % DD;
        smem[O_WIH0T + k * G3 + j] = Wih0[i];
    }
    for (int i = tid; i < G3 * HH; i += THREADS) {
        int j = i / HH, k = i % HH;
        smem[O_WHH0T + k * G3 + j] = Whh0[i];
        smem[O_WIH1T + k * G3 + j] = Wih1[i];
        smem[O_WHH1T + k * G3 + j] = Whh1[i];
    }
    if (tid < G3) {
        smem[O_BI0 + tid] = bih0[tid];
        smem[O_BH0 + tid] = bhh0[tid];
        smem[O_BI1 + tid] = bih1[tid];
        smem[O_BH1 + tid] = bhh1[tid];
    }
    __syncthreads();

    const int warp = tid >> 5;
    const int lane = tid & 31;
    const int b0 = blockIdx.x * BATCH_PER_BLOCK + warp * RB;
    const int u0 = 2 * lane;
    const int u1 = u0 + 1;

    float* h1b = smem + O_HBUF + warp * HBUF_PER_WARP;   // [RB][64]
    float* h2b = h1b + RB * HH;                          // [RB][64]

    // zero warp-private state buffers
    for (int i = lane; i < HBUF_PER_WARP; i += 32)
        h1b[i] = 0.0f;
    __syncwarp();

    // bias constants (combined for r,z; separate x/h parts for n)
    const float rb0A = smem[O_BI0 + u0] + smem[O_BH0 + u0];
    const float rb0B = smem[O_BI0 + u1] + smem[O_BH0 + u1];
    const float zb0A = smem[O_BI0 + 64 + u0] + smem[O_BH0 + 64 + u0];
    const float zb0B = smem[O_BI0 + 64 + u1] + smem[O_BH0 + 64 + u1];
    const float nxb0A = smem[O_BI0 + 128 + u0];
    const float nxb0B = smem[O_BI0 + 128 + u1];
    const float nhb0A = smem[O_BH0 + 128 + u0];
    const float nhb0B = smem[O_BH0 + 128 + u1];

    const float rb1A = smem[O_BI1 + u0] + smem[O_BH1 + u0];
    const float rb1B = smem[O_BI1 + u1] + smem[O_BH1 + u1];
    const float zb1A = smem[O_BI1 + 64 + u0] + smem[O_BH1 + 64 + u0];
    const float zb1B = smem[O_BI1 + 64 + u1] + smem[O_BH1 + 64 + u1];
    const float nxb1A = smem[O_BI1 + 128 + u0];
    const float nxb1B = smem[O_BI1 + 128 + u1];
    const float nhb1A = smem[O_BH1 + 128 + u0];
    const float nhb1B = smem[O_BH1 + 128 + u1];

    const float2* wih0 = (const float2*)(smem + O_WIH0T);
    const float2* whh0 = (const float2*)(smem + O_WHH0T);
    const float2* wih1 = (const float2*)(smem + O_WIH1T);
    const float2* whh1 = (const float2*)(smem + O_WHH1T);

    // x prefetch registers
    float xc[RB], xn[RB];
#pragma unroll
    for (int b = 0; b < RB; ++b)
        xc[b] = x[(size_t)(b0 + b) * (TT * DD) + lane];

    float h2A[RB], h2B[RB];   // layer-2 state for the lane's own unit pair
#pragma unroll
    for (int b = 0; b < RB; ++b) { h2A[b] = 0.f; h2B[b] = 0.f; }

    for (int t = 0; t < TT; ++t) {
        if (t + 1 < TT) {
#pragma unroll
            for (int b = 0; b < RB; ++b)
                xn[b] = x[(size_t)(b0 + b) * (TT * DD) + (t + 1) * DD + lane];
        }

        float rA[RB], rB[RB], zA[RB], zB[RB];
        float nxA[RB], nxB[RB], nhA[RB], nhB[RB];

        // ---------------- layer 1 ----------------
#pragma unroll
        for (int b = 0; b < RB; ++b) {
            rA[b] = rb0A; rB[b] = rb0B; zA[b] = zb0A; zB[b] = zb0B;
            nxA[b] = nxb0A; nxB[b] = nxb0B; nhA[b] = nhb0A; nhB[b] = nhb0B;
        }
        mv32_s(wih0, lane, xc, rA, rB, zA, zB, nxA, nxB);
        mv64_s(whh0, h1b, lane, rA, rB, zA, zB, nhA, nhB);

#pragma unroll
        for (int b = 0; b < RB; ++b) {
            float2 hold = *(const float2*)(h1b + b * HH + u0);
            float r0 = sigmoid_f(rA[b]), r1 = sigmoid_f(rB[b]);
            float z0 = sigmoid_f(zA[b]), z1 = sigmoid_f(zB[b]);
            float n0 = tanh_f(nxA[b] + r0 * nhA[b]);
            float n1 = tanh_f(nxB[b] + r1 * nhB[b]);
            float hA = n0 + z0 * (hold.x - n0);
            float hB = n1 + z1 * (hold.y - n1);
            *(float2*)(h1b + b * HH + u0) = make_float2(hA, hB);
        }
        __syncwarp();

        // ---------------- layer 2 ----------------
#pragma unroll
        for (int b = 0; b < RB; ++b) {
            rA[b] = rb1A; rB[b] = rb1B; zA[b] = zb1A; zB[b] = zb1B;
            nxA[b] = nxb1A; nxB[b] = nxb1B; nhA[b] = nhb1A; nhB[b] = nhb1B;
        }
        mv64_s(wih1, h1b, lane, rA, rB, zA, zB, nxA, nxB);
        mv64_s(whh1, h2b, lane, rA, rB, zA, zB, nhA, nhB);

#pragma unroll
        for (int b = 0; b < RB; ++b) {
            float r0 = sigmoid_f(rA[b]), r1 = sigmoid_f(rB[b]);
            float z0 = sigmoid_f(zA[b]), z1 = sigmoid_f(zB[b]);
            float n0 = tanh_f(nxA[b] + r0 * nhA[b]);
            float n1 = tanh_f(nxB[b] + r1 * nhB[b]);
            float hA = n0 + z0 * (h2A[b] - n0);
            float hB = n1 + z1 * (h2B[b] - n1);
            h2A[b] = hA; h2B[b] = hB;
            *(float2*)(h2b + b * HH + u0) = make_float2(hA, hB);
        }
        __syncwarp();

#pragma unroll
        for (int b = 0; b < RB; ++b) xc[b] = xn[b];
    }

    // ---- final FC ----
    float w0 = fcw[u0], w1 = fcw[u1];
    float p[RB];
#pragma unroll
    for (int b = 0; b < RB; ++b)
        p[b] = h2A[b] * w0 + h2B[b] * w1;
#pragma unroll
    for (int off = 16; off > 0; off >>= 1) {
#pragma unroll
        for (int b = 0; b < RB; ++b)
            p[b] += __shfl_xor_sync(FULLMASK, p[b], off);
    }
    if (lane == 0) {
        float bias = fcb[0];
#pragma unroll
        for (int b = 0; b < RB; ++b)
            out[b0 + b] = p[b] + bias;
    }
}

extern "C" void kernel_launch(void* const* d_in, const int* in_sizes, int n_in,
                              void* d_out, int out_size)
{
    const float* x    = (const float*)d_in[0];
    const float* Wih0 = (const float*)d_in[1];
    const float* Whh0 = (const float*)d_in[2];
    const float* bih0 = (const float*)d_in[3];
    const float* bhh0 = (const float*)d_in[4];
    const float* Wih1 = (const float*)d_in[5];
    const float* Whh1 = (const float*)d_in[6];
    const float* bih1 = (const float*)d_in[7];
    const float* bhh1 = (const float*)d_in[8];
    const float* fcw  = (const float*)d_in[9];
    const float* fcb  = (const float*)d_in[10];
    float* out = (float*)d_out;

    cudaFuncSetAttribute(gru_fused_kernel,
                         cudaFuncAttributeMaxDynamicSharedMemorySize, SMEM_BYTES);

    gru_fused_kernel<<<NBLOCKS, THREADS, SMEM_BYTES>>>(
        x, Wih0, Whh0, bih0, bhh0, Wih1, Whh1, bih1, bhh1, fcw, fcb, out);
}

// round 8
// speedup vs baseline: 1.5332x; 1.2103x over previous
#include <cuda_runtime.h>

#define FULLMASK 0xffffffffu

#define TT 128
#define DD 32
#define HH 64
#define G3 192

#define WARPS 4
#define RB 8                 // batches per warp
#define THREADS (WARPS * 32)           // 128
#define BATCH_PER_BLOCK (WARPS * RB)   // 32
#define NBLOCKS 128                    // 4096 / 32

typedef unsigned long long ull;

// ---- smem layout (floats) ----
#define O_WIH0T 0                        // [32][192] transposed
#define O_WHH0T (O_WIH0T + DD * G3)      // [64][192]
#define O_WIH1T (O_WHH0T + HH * G3)      // [64][192]
#define O_WHH1T (O_WIH1T + HH * G3)      // [64][192]
#define O_BI0   (O_WHH1T + HH * G3)
#define O_BH0   (O_BI0 + G3)
#define O_BI1   (O_BH0 + G3)
#define O_BH1   (O_BI1 + G3)
#define O_HBUF  (O_BH1 + G3)             // per warp: h1[RB][64], h2[RB][64]
#define HBUF_PER_WARP (2 * RB * HH)
#define SMEM_FLOATS (O_HBUF + WARPS * HBUF_PER_WARP)
#define SMEM_BYTES (SMEM_FLOATS * 4)

__device__ __forceinline__ float sigmoid_f(float v) {
    float e = __expf(-v);
    return __fdividef(1.0f, 1.0f + e);
}
__device__ __forceinline__ float tanh_f(float v) {
    float e = __expf(-2.0f * v);
    return __fdividef(1.0f - e, 1.0f + e);
}

// ---- packed f32x2 helpers ----
__device__ __forceinline__ void fma2(ull& d, ull a, ull b) {
    asm("fma.rn.f32x2 %0, %1, %2, %0;" : "+l"(d) : "l"(a), "l"(b));
}
__device__ __forceinline__ ull splat2(float v) {
    ull r;
    asm("mov.b64 %0, {%1, %1};" : "=l"(r) : "f"(v));
    return r;
}
__device__ __forceinline__ ull pack2(float lo, float hi) {
    ull r;
    asm("mov.b64 %0, {%1, %2};" : "=l"(r) : "f"(lo), "f"(hi));
    return r;
}
__device__ __forceinline__ float2 unpack2(ull v) {
    float2 f;
    asm("mov.b64 {%0, %1}, %2;" : "=f"(f.x), "=f"(f.y) : "l"(v));
    return f;
}

// gemv over 64-long h vector in warp-private smem hb[RB][64].
// w2: ull(float2) view of transposed weights ([k][192] floats -> rows of 96).
// Lane owns the packed unit pair (2*lane, 2*lane+1).
__device__ __forceinline__ void mv64_f2(
    const ull* __restrict__ w2, const float* __restrict__ hb, int lane,
    ull ar[RB], ull az[RB], ull an[RB])
{
#pragma unroll 4
    for (int m = 0; m < 32; ++m) {
        const ull* rowe = w2 + (2 * m) * 96;
        const ull* rowo = rowe + 96;
        ull wre = rowe[lane], wze = rowe[32 + lane], wne = rowe[64 + lane];
        ull wro = rowo[lane], wzo = rowo[32 + lane], wno = rowo[64 + lane];
#pragma unroll
        for (int b = 0; b < RB; ++b) {
            // broadcast LDS.64 (same address across lanes, N=1)
            float2 hv = *(const float2*)(hb + b * HH + 2 * m);
            ull sa = splat2(hv.x);
            ull sb = splat2(hv.y);
            fma2(ar[b], wre, sa);
            fma2(az[b], wze, sa);
            fma2(an[b], wne, sa);
            fma2(ar[b], wro, sb);
            fma2(az[b], wzo, sb);
            fma2(an[b], wno, sb);
        }
    }
}

// gemv over 32-long x vector held per-lane (lane k owns x[k]).
__device__ __forceinline__ void mv32_f2(
    const ull* __restrict__ w2, int lane, const float xt[RB],
    ull ar[RB], ull az[RB], ull an[RB])
{
#pragma unroll 4
    for (int k = 0; k < 32; ++k) {
        const ull* row = w2 + k * 96;
        ull wr = row[lane], wz = row[32 + lane], wn = row[64 + lane];
#pragma unroll
        for (int b = 0; b < RB; ++b) {
            ull s = splat2(__shfl_sync(FULLMASK, xt[b], k));
            fma2(ar[b], wr, s);
            fma2(az[b], wz, s);
            fma2(an[b], wn, s);
        }
    }
}

extern __shared__ float smem[];

__global__ void __launch_bounds__(THREADS, 1)
gru_fused_kernel(const float* __restrict__ x,
                 const float* __restrict__ Wih0, const float* __restrict__ Whh0,
                 const float* __restrict__ bih0, const float* __restrict__ bhh0,
                 const float* __restrict__ Wih1, const float* __restrict__ Whh1,
                 const float* __restrict__ bih1, const float* __restrict__ bhh1,
                 const float* __restrict__ fcw, const float* __restrict__ fcb,
                 float* __restrict__ out)
{
    const int tid = threadIdx.x;

    // ---- cooperative load: transpose weights into smem ----
    for (int i = tid; i < G3 * DD; i += THREADS) {
        int j = i / DD, k = i % DD;
        smem[O_WIH0T + k * G3 + j] = Wih0[i];
    }
    for (int i = tid; i < G3 * HH; i += THREADS) {
        int j = i / HH, k = i % HH;
        smem[O_WHH0T + k * G3 + j] = Whh0[i];
        smem[O_WIH1T + k * G3 + j] = Wih1[i];
        smem[O_WHH1T + k * G3 + j] = Whh1[i];
    }
    if (tid < 128) {
        // 192 biases x 4 arrays with 128 threads: strided
        for (int i = tid; i < G3; i += THREADS) {
            smem[O_BI0 + i] = bih0[i];
            smem[O_BH0 + i] = bhh0[i];
            smem[O_BI1 + i] = bih1[i];
            smem[O_BH1 + i] = bhh1[i];
        }
    }
    __syncthreads();

    const int warp = tid >> 5;
    const int lane = tid & 31;
    const int b0 = blockIdx.x * BATCH_PER_BLOCK + warp * RB;
    const int u0 = 2 * lane;
    const int u1 = u0 + 1;

    float* h1b = smem + O_HBUF + warp * HBUF_PER_WARP;   // [RB][64]
    float* h2b = h1b + RB * HH;                          // [RB][64]

    // zero warp-private state buffers
    for (int i = lane; i < HBUF_PER_WARP; i += 32)
        h1b[i] = 0.0f;
    __syncwarp();

    // packed bias constants (unit pair of this lane)
    const ull br0  = pack2(smem[O_BI0 + u0] + smem[O_BH0 + u0],
                           smem[O_BI0 + u1] + smem[O_BH0 + u1]);
    const ull bz0  = pack2(smem[O_BI0 + 64 + u0] + smem[O_BH0 + 64 + u0],
                           smem[O_BI0 + 64 + u1] + smem[O_BH0 + 64 + u1]);
    const ull bnx0 = pack2(smem[O_BI0 + 128 + u0], smem[O_BI0 + 128 + u1]);
    const ull bnh0 = pack2(smem[O_BH0 + 128 + u0], smem[O_BH0 + 128 + u1]);

    const ull br1  = pack2(smem[O_BI1 + u0] + smem[O_BH1 + u0],
                           smem[O_BI1 + u1] + smem[O_BH1 + u1]);
    const ull bz1  = pack2(smem[O_BI1 + 64 + u0] + smem[O_BH1 + 64 + u0],
                           smem[O_BI1 + 64 + u1] + smem[O_BH1 + 64 + u1]);
    const ull bnx1 = pack2(smem[O_BI1 + 128 + u0], smem[O_BI1 + 128 + u1]);
    const ull bnh1 = pack2(smem[O_BH1 + 128 + u0], smem[O_BH1 + 128 + u1]);

    const ull* wih0 = (const ull*)(smem + O_WIH0T);
    const ull* whh0 = (const ull*)(smem + O_WHH0T);
    const ull* wih1 = (const ull*)(smem + O_WIH1T);
    const ull* whh1 = (const ull*)(smem + O_WHH1T);

    // x prefetch registers
    float xc[RB], xn[RB];
#pragma unroll
    for (int b = 0; b < RB; ++b)
        xc[b] = x[(size_t)(b0 + b) * (TT * DD) + lane];

    float h2A[RB], h2B[RB];   // layer-2 state for the lane's own unit pair
#pragma unroll
    for (int b = 0; b < RB; ++b) { h2A[b] = 0.f; h2B[b] = 0.f; }

    for (int t = 0; t < TT; ++t) {
        if (t + 1 < TT) {
#pragma unroll
            for (int b = 0; b < RB; ++b)
                xn[b] = x[(size_t)(b0 + b) * (TT * DD) + (t + 1) * DD + lane];
        }

        ull ar[RB], az[RB], anx[RB], anh[RB];

        // ---------------- layer 1 ----------------
#pragma unroll
        for (int b = 0; b < RB; ++b) {
            ar[b] = br0; az[b] = bz0; anx[b] = bnx0; anh[b] = bnh0;
        }
        mv32_f2(wih0, lane, xc, ar, az, anx);
        mv64_f2(whh0, h1b, lane, ar, az, anh);

#pragma unroll
        for (int b = 0; b < RB; ++b) {
            float2 rv = unpack2(ar[b]);
            float2 zv = unpack2(az[b]);
            float2 nx = unpack2(anx[b]);
            float2 nh = unpack2(anh[b]);
            float2 hold = *(const float2*)(h1b + b * HH + u0);  // own pair
            float r0 = sigmoid_f(rv.x), r1 = sigmoid_f(rv.y);
            float z0 = sigmoid_f(zv.x), z1 = sigmoid_f(zv.y);
            float n0 = tanh_f(nx.x + r0 * nh.x);
            float n1 = tanh_f(nx.y + r1 * nh.y);
            float hA = n0 + z0 * (hold.x - n0);
            float hB = n1 + z1 * (hold.y - n1);
            *(float2*)(h1b + b * HH + u0) = make_float2(hA, hB);
        }
        __syncwarp();

        // ---------------- layer 2 ----------------
#pragma unroll
        for (int b = 0; b < RB; ++b) {
            ar[b] = br1; az[b] = bz1; anx[b] = bnx1; anh[b] = bnh1;
        }
        mv64_f2(wih1, h1b, lane, ar, az, anx);
        mv64_f2(whh1, h2b, lane, ar, az, anh);

#pragma unroll
        for (int b = 0; b < RB; ++b) {
            float2 rv = unpack2(ar[b]);
            float2 zv = unpack2(az[b]);
            float2 nx = unpack2(anx[b]);
            float2 nh = unpack2(anh[b]);
            float r0 = sigmoid_f(rv.x), r1 = sigmoid_f(rv.y);
            float z0 = sigmoid_f(zv.x), z1 = sigmoid_f(zv.y);
            float n0 = tanh_f(nx.x + r0 * nh.x);
            float n1 = tanh_f(nx.y + r1 * nh.y);
            float hA = n0 + z0 * (h2A[b] - n0);
            float hB = n1 + z1 * (h2B[b] - n1);
            h2A[b] = hA; h2B[b] = hB;
            *(float2*)(h2b + b * HH + u0) = make_float2(hA, hB);
        }
        __syncwarp();

#pragma unroll
        for (int b = 0; b < RB; ++b) xc[b] = xn[b];
    }

    // ---- final FC ----
    float w0 = fcw[u0], w1 = fcw[u1];
    float p[RB];
#pragma unroll
    for (int b = 0; b < RB; ++b)
        p[b] = h2A[b] * w0 + h2B[b] * w1;
#pragma unroll
    for (int off = 16; off > 0; off >>= 1) {
#pragma unroll
        for (int b = 0; b < RB; ++b)
            p[b] += __shfl_xor_sync(FULLMASK, p[b], off);
    }
    if (lane == 0) {
        float bias = fcb[0];
#pragma unroll
        for (int b = 0; b < RB; ++b)
            out[b0 + b] = p[b] + bias;
    }
}

extern "C" void kernel_launch(void* const* d_in, const int* in_sizes, int n_in,
                              void* d_out, int out_size)
{
    const float* x    = (const float*)d_in[0];
    const float* Wih0 = (const float*)d_in[1];
    const float* Whh0 = (const float*)d_in[2];
    const float* bih0 = (const float*)d_in[3];
    const float* bhh0 = (const float*)d_in[4];
    const float* Wih1 = (const float*)d_in[5];
    const float* Whh1 = (const float*)d_in[6];
    const float* bih1 = (const float*)d_in[7];
    const float* bhh1 = (const float*)d_in[8];
    const float* fcw  = (const float*)d_in[9];
    const float* fcb  = (const float*)d_in[10];
    float* out = (float*)d_out;

    cudaFuncSetAttribute(gru_fused_kernel,
                         cudaFuncAttributeMaxDynamicSharedMemorySize, SMEM_BYTES);

    gru_fused_kernel<<<NBLOCKS, THREADS, SMEM_BYTES>>>(
        x, Wih0, Whh0, bih0, bhh0, Wih1, Whh1, bih1, bhh1, fcw, fcb, out);
}

// round 11
// speedup vs baseline: 1.7177x; 1.1204x over previous
#include <cuda_runtime.h>

#define FULLMASK 0xffffffffu

#define TT 128
#define DD 32
#define HH 64
#define G3 192

#define WARPS 8
#define RB 4                 // batches per warp
#define THREADS (WARPS * 32)           // 256
#define BATCH_PER_BLOCK (WARPS * RB)   // 32
#define NBLOCKS 128                    // 4096 / 32

typedef unsigned long long ull;

// ---- smem layout (floats) ----
#define O_WIH0T 0                        // [32][192] transposed
#define O_WHH0T (O_WIH0T + DD * G3)      // [64][192]
#define O_WIH1T (O_WHH0T + HH * G3)      // [64][192]
#define O_WHH1T (O_WIH1T + HH * G3)      // [64][192]
#define O_BI0   (O_WHH1T + HH * G3)
#define O_BH0   (O_BI0 + G3)
#define O_BI1   (O_BH0 + G3)
#define O_BH1   (O_BI1 + G3)
#define O_HBUF  (O_BH1 + G3)             // per warp: h1[RB][64], h2[RB][64], x[RB][32]
#define HBUF_PER_WARP (2 * RB * HH + RB * DD)
#define SMEM_FLOATS (O_HBUF + WARPS * HBUF_PER_WARP)
#define SMEM_BYTES (SMEM_FLOATS * 4)

__device__ __forceinline__ float sigmoid_f(float v) {
    float e = __expf(-v);
    return __fdividef(1.0f, 1.0f + e);
}
__device__ __forceinline__ float tanh_f(float v) {
    float e = __expf(-2.0f * v);
    return __fdividef(1.0f - e, 1.0f + e);
}

// ---- packed f32x2 helpers ----
__device__ __forceinline__ void fma2(ull& d, ull a, ull b) {
    asm("fma.rn.f32x2 %0, %1, %2, %0;" : "+l"(d) : "l"(a), "l"(b));
}
__device__ __forceinline__ ull splat2(float v) {
    ull r;
    asm("mov.b64 %0, {%1, %1};" : "=l"(r) : "f"(v));
    return r;
}
__device__ __forceinline__ ull pack2(float lo, float hi) {
    ull r;
    asm("mov.b64 %0, {%1, %2};" : "=l"(r) : "f"(lo), "f"(hi));
    return r;
}
__device__ __forceinline__ float2 unpack2(ull v) {
    float2 f;
    asm("mov.b64 {%0, %1}, %2;" : "=f"(f.x), "=f"(f.y) : "l"(v));
    return f;
}

// gemv over an L-long vector held in warp-private smem buffer vb[RB][L].
// w2: ull(float2) view of transposed weights ([k][192] floats -> rows of 96).
// Lane owns the packed unit pair (2*lane, 2*lane+1); accumulates 3 gates x RB.
template <int L>
__device__ __forceinline__ void mv_f2(
    const ull* __restrict__ w2, const float* __restrict__ vb, int lane,
    ull ar[RB], ull az[RB], ull an[RB])
{
#pragma unroll 4
    for (int m = 0; m < L / 2; ++m) {
        const ull* rowe = w2 + (2 * m) * 96;
        const ull* rowo = rowe + 96;
        ull wre = rowe[lane], wze = rowe[32 + lane], wne = rowe[64 + lane];
        ull wro = rowo[lane], wzo = rowo[32 + lane], wno = rowo[64 + lane];
#pragma unroll
        for (int b = 0; b < RB; ++b) {
            // broadcast LDS.64 (same address across lanes, N=1)
            float2 hv = *(const float2*)(vb + b * L + 2 * m);
            ull sa = splat2(hv.x);
            ull sb = splat2(hv.y);
            fma2(ar[b], wre, sa);
            fma2(az[b], wze, sa);
            fma2(an[b], wne, sa);
            fma2(ar[b], wro, sb);
            fma2(az[b], wzo, sb);
            fma2(an[b], wno, sb);
        }
    }
}

extern __shared__ float smem[];

__global__ void __launch_bounds__(THREADS, 1)
gru_fused_kernel(const float* __restrict__ x,
                 const float* __restrict__ Wih0, const float* __restrict__ Whh0,
                 const float* __restrict__ bih0, const float* __restrict__ bhh0,
                 const float* __restrict__ Wih1, const float* __restrict__ Whh1,
                 const float* __restrict__ bih1, const float* __restrict__ bhh1,
                 const float* __restrict__ fcw, const float* __restrict__ fcb,
                 float* __restrict__ out)
{
    const int tid = threadIdx.x;

    // ---- cooperative load: transpose weights into smem ----
    for (int i = tid; i < G3 * DD; i += THREADS) {
        int j = i / DD, k = i % DD;
        smem[O_WIH0T + k * G3 + j] = Wih0[i];
    }
    for (int i = tid; i < G3 * HH; i += THREADS) {
        int j = i / HH, k = i % HH;
        smem[O_WHH0T + k * G3 + j] = Whh0[i];
        smem[O_WIH1T + k * G3 + j] = Wih1[i];
        smem[O_WHH1T + k * G3 + j] = Whh1[i];
    }
    for (int i = tid; i < G3; i += THREADS) {
        smem[O_BI0 + i] = bih0[i];
        smem[O_BH0 + i] = bhh0[i];
        smem[O_BI1 + i] = bih1[i];
        smem[O_BH1 + i] = bhh1[i];
    }
    __syncthreads();

    const int warp = tid >> 5;
    const int lane = tid & 31;
    const int b0 = blockIdx.x * BATCH_PER_BLOCK + warp * RB;
    const int u0 = 2 * lane;
    const int u1 = u0 + 1;

    float* h1b  = smem + O_HBUF + warp * HBUF_PER_WARP;  // [RB][64]
    float* h2b  = h1b + RB * HH;                          // [RB][64]
    float* xbuf = h2b + RB * HH;                          // [RB][32]

    // zero warp-private state buffers
    for (int i = lane; i < HBUF_PER_WARP; i += 32)
        h1b[i] = 0.0f;
    __syncwarp();

    // packed bias constants (unit pair of this lane)
    const ull br0  = pack2(smem[O_BI0 + u0] + smem[O_BH0 + u0],
                           smem[O_BI0 + u1] + smem[O_BH0 + u1]);
    const ull bz0  = pack2(smem[O_BI0 + 64 + u0] + smem[O_BH0 + 64 + u0],
                           smem[O_BI0 + 64 + u1] + smem[O_BH0 + 64 + u1]);
    const ull bnx0 = pack2(smem[O_BI0 + 128 + u0], smem[O_BI0 + 128 + u1]);
    const ull bnh0 = pack2(smem[O_BH0 + 128 + u0], smem[O_BH0 + 128 + u1]);

    const ull br1  = pack2(smem[O_BI1 + u0] + smem[O_BH1 + u0],
                           smem[O_BI1 + u1] + smem[O_BH1 + u1]);
    const ull bz1  = pack2(smem[O_BI1 + 64 + u0] + smem[O_BH1 + 64 + u0],
                           smem[O_BI1 + 64 + u1] + smem[O_BH1 + 64 + u1]);
    const ull bnx1 = pack2(smem[O_BI1 + 128 + u0], smem[O_BI1 + 128 + u1]);
    const ull bnh1 = pack2(smem[O_BH1 + 128 + u0], smem[O_BH1 + 128 + u1]);

    const ull* wih0 = (const ull*)(smem + O_WIH0T);
    const ull* whh0 = (const ull*)(smem + O_WHH0T);
    const ull* wih1 = (const ull*)(smem + O_WIH1T);
    const ull* whh1 = (const ull*)(smem + O_WHH1T);

    // x prefetch registers
    float xc[RB], xn[RB];
#pragma unroll
    for (int b = 0; b < RB; ++b)
        xc[b] = x[(size_t)(b0 + b) * (TT * DD) + lane];

    float h2A[RB], h2B[RB];   // layer-2 state for the lane's own unit pair
#pragma unroll
    for (int b = 0; b < RB; ++b) { h2A[b] = 0.f; h2B[b] = 0.f; }

    for (int t = 0; t < TT; ++t) {
        // stage current x into warp-private smem for broadcast reads
#pragma unroll
        for (int b = 0; b < RB; ++b)
            xbuf[b * DD + lane] = xc[b];
        __syncwarp();

        // prefetch next timestep's x
        if (t + 1 < TT) {
#pragma unroll
            for (int b = 0; b < RB; ++b)
                xn[b] = x[(size_t)(b0 + b) * (TT * DD) + (t + 1) * DD + lane];
        }

        ull ar[RB], az[RB], anx[RB], anh[RB];

        // ---------------- layer 1 ----------------
#pragma unroll
        for (int b = 0; b < RB; ++b) {
            ar[b] = br0; az[b] = bz0; anx[b] = bnx0; anh[b] = bnh0;
        }
        mv_f2<DD>(wih0, xbuf, lane, ar, az, anx);
        mv_f2<HH>(whh0, h1b, lane, ar, az, anh);

#pragma unroll
        for (int b = 0; b < RB; ++b) {
            float2 rv = unpack2(ar[b]);
            float2 zv = unpack2(az[b]);
            float2 nx = unpack2(anx[b]);
            float2 nh = unpack2(anh[b]);
            float2 hold = *(const float2*)(h1b + b * HH + u0);  // own pair
            float r0 = sigmoid_f(rv.x), r1 = sigmoid_f(rv.y);
            float z0 = sigmoid_f(zv.x), z1 = sigmoid_f(zv.y);
            float n0 = tanh_f(nx.x + r0 * nh.x);
            float n1 = tanh_f(nx.y + r1 * nh.y);
            float hA = n0 + z0 * (hold.x - n0);
            float hB = n1 + z1 * (hold.y - n1);
            *(float2*)(h1b + b * HH + u0) = make_float2(hA, hB);
        }
        __syncwarp();

        // ---------------- layer 2 ----------------
#pragma unroll
        for (int b = 0; b < RB; ++b) {
            ar[b] = br1; az[b] = bz1; anx[b] = bnx1; anh[b] = bnh1;
        }
        mv_f2<HH>(wih1, h1b, lane, ar, az, anx);
        mv_f2<HH>(whh1, h2b, lane, ar, az, anh);

#pragma unroll
        for (int b = 0; b < RB; ++b) {
            float2 rv = unpack2(ar[b]);
            float2 zv = unpack2(az[b]);
            float2 nx = unpack2(anx[b]);
            float2 nh = unpack2(anh[b]);
            float r0 = sigmoid_f(rv.x), r1 = sigmoid_f(rv.y);
            float z0 = sigmoid_f(zv.x), z1 = sigmoid_f(zv.y);
            float n0 = tanh_f(nx.x + r0 * nh.x);
            float n1 = tanh_f(nx.y + r1 * nh.y);
            float hA = n0 + z0 * (h2A[b] - n0);
            float hB = n1 + z1 * (h2B[b] - n1);
            h2A[b] = hA; h2B[b] = hB;
            *(float2*)(h2b + b * HH + u0) = make_float2(hA, hB);
        }
        __syncwarp();

#pragma unroll
        for (int b = 0; b < RB; ++b) xc[b] = xn[b];
    }

    // ---- final FC ----
    float w0 = fcw[u0], w1 = fcw[u1];
    float p[RB];
#pragma unroll
    for (int b = 0; b < RB; ++b)
        p[b] = h2A[b] * w0 + h2B[b] * w1;
#pragma unroll
    for (int off = 16; off > 0; off >>= 1) {
#pragma unroll
        for (int b = 0; b < RB; ++b)
            p[b] += __shfl_xor_sync(FULLMASK, p[b], off);
    }
    if (lane == 0) {
        float bias = fcb[0];
#pragma unroll
        for (int b = 0; b < RB; ++b)
            out[b0 + b] = p[b] + bias;
    }
}

extern "C" void kernel_launch(void* const* d_in, const int* in_sizes, int n_in,
                              void* d_out, int out_size)
{
    const float* x    = (const float*)d_in[0];
    const float* Wih0 = (const float*)d_in[1];
    const float* Whh0 = (const float*)d_in[2];
    const float* bih0 = (const float*)d_in[3];
    const float* bhh0 = (const float*)d_in[4];
    const float* Wih1 = (const float*)d_in[5];
    const float* Whh1 = (const float*)d_in[6];
    const float* bih1 = (const float*)d_in[7];
    const float* bhh1 = (const float*)d_in[8];
    const float* fcw  = (const float*)d_in[9];
    const float* fcb  = (const float*)d_in[10];
    float* out = (float*)d_out;

    cudaFuncSetAttribute(gru_fused_kernel,
                         cudaFuncAttributeMaxDynamicSharedMemorySize, SMEM_BYTES);

    gru_fused_kernel<<<NBLOCKS, THREADS, SMEM_BYTES>>>(
        x, Wih0, Whh0, bih0, bhh0, Wih1, Whh1, bih1, bhh1, fcw, fcb, out);
}